// round 1
// baseline (speedup 1.0000x reference)
#include <cuda_runtime.h>
#include <cub/cub.cuh>

// ---------------- problem constants ----------------
#define BB 4
#define KK 8
#define HH 512
#define WW 1024
#define NPIX (HH * WW)                 // 524288
#define NSEG (BB * KK)                 // 32
#define NTOT ((size_t)NSEG * NPIX)     // 16777216
#define CHUNK 4096
#define NCHUNK ((int)(NTOT / CHUNK))   // 4096
#define CPS (NPIX / CHUNK)             // 128 chunks per segment

#define XSTEP (2.0f / 2047.0f)         // linspace(0,2,2048)
#define YSTEP (1.0f / 1023.0f)         // linspace(0,1,1024)

// ---------------- static device scratch (no allocs allowed) ----------------
__device__ unsigned long long g_keysA[NTOT];          // 134 MB
__device__ unsigned long long g_keysB[NTOT];          // 134 MB
__device__ unsigned long long g_cubtemp[1 << 25];     // 256 MB, 8B-aligned
__device__ unsigned int g_cnt[NSEG];
__device__ float g_sumx[NSEG], g_sumy[NSEG], g_sumsig[NSEG];
__device__ float g_cx[NSEG], g_cy[NSEG], g_smean[NSEG], g_sexp[NSEG];
__device__ double g_bg[BB];
__device__ double g_var[NSEG], g_fg[NSEG], g_lov[NSEG];
__device__ unsigned int g_ccnt[NCHUNK], g_coff[NCHUNK];

// ---------------- kernel 0: zero accumulators ----------------
__global__ void k_zero() {
    int t = threadIdx.x;
    if (t < NSEG) {
        g_cnt[t] = 0u;
        g_sumx[t] = 0.f; g_sumy[t] = 0.f; g_sumsig[t] = 0.f;
        g_var[t] = 0.0; g_fg[t] = 0.0; g_lov[t] = 0.0;
    }
    if (t < BB) g_bg[t] = 0.0;
}

// ---------------- kernel 1: per-(b,k) mask statistics ----------------
// counts, sum of x-coord, sum of y-coord, sum of sigma over each instance mask
__global__ void k_stats(const float* __restrict__ pred, const int* __restrict__ ins) {
    int b = blockIdx.y;
    __shared__ unsigned int s_cnt[KK];
    __shared__ float s_x[KK], s_y[KK], s_s[KK];
    if (threadIdx.x < KK) {
        s_cnt[threadIdx.x] = 0u;
        s_x[threadIdx.x] = 0.f; s_y[threadIdx.x] = 0.f; s_s[threadIdx.x] = 0.f;
    }
    __syncthreads();

    const float* sigma = pred + ((size_t)b * 4 + 2) * NPIX;
    const int* ib = ins + (size_t)b * NPIX;
    int base = blockIdx.x * 2048;
#pragma unroll
    for (int j = 0; j < 8; j++) {
        int p = base + j * 256 + threadIdx.x;
        int id = ib[p];
        if (id > 0 && id <= KK) {
            int k = id - 1;
            int w = p & (WW - 1);
            int h = p >> 10;
            atomicAdd(&s_cnt[k], 1u);
            atomicAdd(&s_x[k], (float)w * XSTEP);
            atomicAdd(&s_y[k], (float)h * YSTEP);
            atomicAdd(&s_s[k], sigma[p]);
        }
    }
    __syncthreads();
    if (threadIdx.x < KK) {
        int s = b * KK + threadIdx.x;
        atomicAdd(&g_cnt[s], s_cnt[threadIdx.x]);
        atomicAdd(&g_sumx[s], s_x[threadIdx.x]);
        atomicAdd(&g_sumy[s], s_y[threadIdx.x]);
        atomicAdd(&g_sumsig[s], s_s[threadIdx.x]);
    }
}

// ---------------- kernel 2: centers / s_mean / s_exp ----------------
__global__ void k_centers() {
    int s = threadIdx.x;
    if (s >= NSEG) return;
    float c = fmaxf((float)g_cnt[s], 1.0f);
    g_cx[s] = g_sumx[s] / c;
    g_cy[s] = g_sumy[s] / c;
    float sm = g_sumsig[s] / c;
    g_smean[s] = sm;
    g_sexp[s] = expf(10.0f * sm);
}

// ---------------- kernel 3: per-pixel main pass ----------------
// emits 8 sort keys per pixel, accumulates var / seed_fg / seed_bg
__global__ void k_main(const float* __restrict__ pred, const int* __restrict__ ins,
                       const int* __restrict__ lab) {
    int b = blockIdx.y;
    int p = blockIdx.x * 256 + threadIdx.x;

    __shared__ float s_cx[KK], s_cy[KK], s_sx[KK], s_sm[KK];
    __shared__ float s_var[KK], s_fg[KK];
    __shared__ float s_bg;
    if (threadIdx.x < KK) {
        int s = b * KK + threadIdx.x;
        s_cx[threadIdx.x] = g_cx[s];
        s_cy[threadIdx.x] = g_cy[s];
        s_sx[threadIdx.x] = g_sexp[s];
        s_sm[threadIdx.x] = g_smean[s];
        s_var[threadIdx.x] = 0.f;
        s_fg[threadIdx.x] = 0.f;
    }
    if (threadIdx.x == 0) s_bg = 0.f;
    __syncthreads();

    const float* pb = pred + (size_t)b * 4 * NPIX;
    float p0 = pb[p];
    float p1 = pb[NPIX + p];
    float sig = pb[2 * NPIX + p];
    float p3 = pb[3 * NPIX + p];
    int id = ins[(size_t)b * NPIX + p];
    int lb = lab[(size_t)b * NPIX + p];

    float ex = tanhf(p0) + (float)(p & (WW - 1)) * XSTEP;
    float ey = tanhf(p1) + (float)(p >> 10) * YSTEP;
    float seed = 1.0f / (1.0f + expf(-p3));

    if (lb == 0) atomicAdd(&s_bg, seed * seed);

    int myk = (id > 0 && id <= KK) ? id - 1 : -1;
    if (myk >= 0) {
        float dv = sig - s_sm[myk];
        atomicAdd(&s_var[myk], dv * dv);
    }

#pragma unroll
    for (int k = 0; k < KK; k++) {
        float dx = ex - s_cx[k];
        float dy = ey - s_cy[k];
        float d2 = dx * dx + dy * dy;
        float dist = __expf(-s_sx[k] * d2);
        int l = (k == myk) ? 1 : 0;
        // lovasz errors: fg -> 2-2d, bg -> 2d, all >= 0
        float e = l ? (2.0f - 2.0f * dist) : (2.0f * dist);
        unsigned int eb = __float_as_uint(e);
        unsigned long long key =
            ((unsigned long long)(b * KK + k) << 33) |
            ((unsigned long long)(~eb) << 1) |
            (unsigned long long)l;
        g_keysA[(size_t)(b * KK + k) * NPIX + p] = key;
        if (l) {
            float df = seed - dist;
            atomicAdd(&s_fg[myk], df * df);
        }
    }
    __syncthreads();
    if (threadIdx.x < KK) {
        int s = b * KK + threadIdx.x;
        atomicAdd(&g_var[s], (double)s_var[threadIdx.x]);
        atomicAdd(&g_fg[s], (double)s_fg[threadIdx.x]);
    }
    if (threadIdx.x == 0) atomicAdd(&g_bg[b], (double)s_bg);
}

// ---------------- block reduce helper ----------------
__device__ __forceinline__ float block_reduce_f(float v, float* sh) {
    int lane = threadIdx.x & 31, wid = threadIdx.x >> 5;
#pragma unroll
    for (int o = 16; o > 0; o >>= 1) v += __shfl_down_sync(0xffffffffu, v, o);
    if (lane == 0) sh[wid] = v;
    __syncthreads();
    if (wid == 0) {
        v = (lane < (blockDim.x >> 5)) ? sh[lane] : 0.f;
#pragma unroll
        for (int o = 4; o > 0; o >>= 1) v += __shfl_down_sync(0xffffffffu, v, o);
    }
    return v;
}

// ---------------- kernel 5: per-chunk label counts (post-sort) ----------------
__global__ void k_ccount(const unsigned long long* __restrict__ keys) {
    size_t base = (size_t)blockIdx.x * CHUNK + (size_t)threadIdx.x * 16;
    const ulonglong2* kp = (const ulonglong2*)(keys + base);
    int c = 0;
#pragma unroll
    for (int j = 0; j < 8; j++) {
        ulonglong2 v = kp[j];
        c += (int)(v.x & 1ull) + (int)(v.y & 1ull);
    }
    __shared__ float sh[8];
    float r = block_reduce_f((float)c, sh);
    if (threadIdx.x == 0) g_ccnt[blockIdx.x] = (unsigned int)r;
}

// ---------------- kernel 6: exclusive prefix of chunk counts per segment ----------------
__global__ void k_cscan() {
    int s = threadIdx.x;
    if (s >= NSEG) return;
    unsigned int off = 0;
    for (int c = 0; c < CPS; c++) {
        unsigned int v = g_ccnt[s * CPS + c];
        g_coff[s * CPS + c] = off;
        off += v;
    }
}

// ---------------- kernel 7: Lovasz loss over sorted keys ----------------
// grad_i = l ? 1/U : (G-P)/(U*(U-1)),  U = G + i - P_i  (exact, no cancellation)
__global__ void k_loss(const unsigned long long* __restrict__ keys) {
    int chunk = blockIdx.x;
    int seg = chunk >> 7;  // CPS = 128
    unsigned int G = g_cnt[seg];
    if (G == 0) return;  // where(present, lov, 0) -> skip
    float fG = (float)G;

    size_t base = (size_t)chunk * CHUNK + (size_t)threadIdx.x * 16;
    const ulonglong2* kp = (const ulonglong2*)(keys + base);
    unsigned long long v[16];
#pragma unroll
    for (int j = 0; j < 8; j++) {
        ulonglong2 t = kp[j];
        v[2 * j] = t.x;
        v[2 * j + 1] = t.y;
    }
    int lc = 0;
#pragma unroll
    for (int j = 0; j < 16; j++) lc += (int)(v[j] & 1ull);

    // block-wide exclusive scan of per-thread label counts
    int lane = threadIdx.x & 31, wid = threadIdx.x >> 5;
    int x = lc;
#pragma unroll
    for (int o = 1; o < 32; o <<= 1) {
        int y = __shfl_up_sync(0xffffffffu, x, o);
        if (lane >= o) x += y;
    }
    __shared__ int wsum[8];
    if (lane == 31) wsum[wid] = x;
    __syncthreads();
    if (threadIdx.x < 8) {
        int w = wsum[threadIdx.x];
#pragma unroll
        for (int o = 1; o < 8; o <<= 1) {
            int y = __shfl_up_sync(0x000000ffu, w, o);
            if ((int)threadIdx.x >= o) w += y;
        }
        wsum[threadIdx.x] = w;
    }
    __syncthreads();
    int excl = x - lc + (wid > 0 ? wsum[wid - 1] : 0);

    unsigned int P = g_coff[chunk] + (unsigned int)excl;       // fg count before my 1st elem
    unsigned int i0 = (unsigned int)(chunk & (CPS - 1)) * CHUNK + threadIdx.x * 16;  // 0-based pos in segment

    float acc = 0.f;
#pragma unroll
    for (int j = 0; j < 16; j++) {
        int l = (int)(v[j] & 1ull);
        P += (unsigned int)l;
        float e = __uint_as_float(~(unsigned int)(v[j] >> 1));
        float fi = (float)(i0 + j + 1);  // 1-indexed rank
        float fP = (float)P;
        float U = fG + fi - fP;
        float grad = l ? __fdividef(1.0f, U)
                       : __fdividef(fG - fP, U * (U - 1.0f));
        acc += e * grad;  // e >= 0 always, relu is identity
    }
    __shared__ float sh[8];
    float r = block_reduce_f(acc, sh);
    if (threadIdx.x == 0) atomicAdd(&g_lov[seg], (double)r);
}

// ---------------- kernel 8: final combination ----------------
__global__ void k_final(float* __restrict__ out) {
    if (threadIdx.x != 0) return;
    double tot = 0.0;
    for (int b = 0; b < BB; b++) {
        int np = 0;
        double inst = 0.0, var = 0.0, fg = 0.0;
        for (int k = 0; k < KK; k++) {
            int s = b * KK + k;
            unsigned int c = g_cnt[s];
            if (c > 0) {
                np++;
                inst += g_lov[s];
                var += g_var[s] / (double)c;
                fg += g_fg[s];
            }
        }
        double objf = (np > 0) ? (double)np : 1.0;
        double seed = (g_bg[b] + fg) / (double)NPIX;  // FG_W = 1
        tot += inst / objf + 10.0 * var / objf + seed; // W_INST=1, W_VAR=10, W_SEED=1
    }
    out[0] = (float)(tot / BB);
}

// ---------------- launch ----------------
extern "C" void kernel_launch(void* const* d_in, const int* in_sizes, int n_in,
                              void* d_out, int out_size) {
    const float* pred = (const float*)d_in[0];
    const int* ins = (const int*)d_in[1];
    const int* lab = (const int*)d_in[2];
    float* out = (float*)d_out;
    cudaStream_t st = 0;

    k_zero<<<1, 64, 0, st>>>();
    k_stats<<<dim3(NPIX / 2048, BB), 256, 0, st>>>(pred, ins);
    k_centers<<<1, 32, 0, st>>>();
    k_main<<<dim3(NPIX / 256, BB), 256, 0, st>>>(pred, ins, lab);

    void *pa, *pb, *pt;
    cudaGetSymbolAddress(&pa, g_keysA);
    cudaGetSymbolAddress(&pb, g_keysB);
    cudaGetSymbolAddress(&pt, g_cubtemp);

    cub::DoubleBuffer<unsigned long long> dk((unsigned long long*)pa,
                                             (unsigned long long*)pb);
    size_t tb = 0;
    cub::DeviceRadixSort::SortKeys(nullptr, tb, dk, (int)NTOT, 0, 38, st);
    if (tb > sizeof(g_cubtemp)) tb = sizeof(g_cubtemp);  // static buffer is generous
    cub::DeviceRadixSort::SortKeys(pt, tb, dk, (int)NTOT, 0, 38, st);
    const unsigned long long* sorted = dk.Current();

    k_ccount<<<NCHUNK, 256, 0, st>>>(sorted);
    k_cscan<<<1, 32, 0, st>>>();
    k_loss<<<NCHUNK, 256, 0, st>>>(sorted);
    k_final<<<1, 32, 0, st>>>(out);
}

// round 2
// speedup vs baseline: 6.3291x; 6.3291x over previous
#include <cuda_runtime.h>

// ---------------- problem constants ----------------
#define BB 4
#define KK 8
#define HH 512
#define WW 1024
#define NPIX (HH * WW)                 // 524288
#define NSEG (BB * KK)                 // 32
#define QBIN 65536                     // error-quantization bins
#define DELTA (2.0f / 65536.0f)        // bin width over e in [0,2]
#define CH 2048                        // bins per scan chunk
#define CPSG (QBIN / CH)               // 32 chunks per segment
#define NCHB (NSEG * CPSG)             // 1024 chunks

#define XSTEP (2.0f / 2047.0f)         // linspace(0,2,2048)
#define YSTEP (1.0f / 1023.0f)         // linspace(0,1,1024)

// ---------------- static device scratch ----------------
// hist[seg][r]: r = rank (0 = largest error). Packed u64: ctot in lo32, cfg in hi32.
__device__ unsigned long long g_hist[(size_t)NSEG * QBIN];   // 16 MB
__device__ unsigned int g_cnt[NSEG];
__device__ float g_sumx[NSEG], g_sumy[NSEG], g_sumsig[NSEG];
__device__ float g_cx[NSEG], g_cy[NSEG], g_smean[NSEG], g_sexp[NSEG];
__device__ double g_bg[BB];
__device__ double g_var[NSEG], g_fg[NSEG], g_lovS[NSEG];
__device__ unsigned int g_chT[NCHB], g_chF[NCHB];
__device__ unsigned int g_offT[NCHB], g_offF[NCHB];

// ---------------- kernel: zero small accumulators ----------------
__global__ void k_zero() {
    int t = threadIdx.x;
    if (t < NSEG) {
        g_cnt[t] = 0u;
        g_sumx[t] = 0.f; g_sumy[t] = 0.f; g_sumsig[t] = 0.f;
        g_var[t] = 0.0; g_fg[t] = 0.0; g_lovS[t] = 0.0;
    }
    if (t < BB) g_bg[t] = 0.0;
}

// ---------------- kernel: zero histogram (16 MB) ----------------
__global__ void k_hzero() {
    size_t i = ((size_t)blockIdx.x * 256 + threadIdx.x) * 2;
    ulonglong2 z; z.x = 0ull; z.y = 0ull;
    *(ulonglong2*)(g_hist + i) = z;
}

// ---------------- kernel: per-(b,k) mask statistics ----------------
__global__ void k_stats(const float* __restrict__ pred, const int* __restrict__ ins) {
    int b = blockIdx.y;
    __shared__ unsigned int s_cnt[KK];
    __shared__ float s_x[KK], s_y[KK], s_s[KK];
    if (threadIdx.x < KK) {
        s_cnt[threadIdx.x] = 0u;
        s_x[threadIdx.x] = 0.f; s_y[threadIdx.x] = 0.f; s_s[threadIdx.x] = 0.f;
    }
    __syncthreads();

    const float* sigma = pred + ((size_t)b * 4 + 2) * NPIX;
    const int* ib = ins + (size_t)b * NPIX;
    int base = blockIdx.x * 2048;
#pragma unroll
    for (int j = 0; j < 8; j++) {
        int p = base + j * 256 + threadIdx.x;
        int id = ib[p];
        if (id > 0 && id <= KK) {
            int k = id - 1;
            int w = p & (WW - 1);
            int h = p >> 10;
            atomicAdd(&s_cnt[k], 1u);
            atomicAdd(&s_x[k], (float)w * XSTEP);
            atomicAdd(&s_y[k], (float)h * YSTEP);
            atomicAdd(&s_s[k], sigma[p]);
        }
    }
    __syncthreads();
    if (threadIdx.x < KK) {
        int s = b * KK + threadIdx.x;
        atomicAdd(&g_cnt[s], s_cnt[threadIdx.x]);
        atomicAdd(&g_sumx[s], s_x[threadIdx.x]);
        atomicAdd(&g_sumy[s], s_y[threadIdx.x]);
        atomicAdd(&g_sumsig[s], s_s[threadIdx.x]);
    }
}

// ---------------- kernel: centers / s_mean / s_exp ----------------
__global__ void k_centers() {
    int s = threadIdx.x;
    if (s >= NSEG) return;
    float c = fmaxf((float)g_cnt[s], 1.0f);
    g_cx[s] = g_sumx[s] / c;
    g_cy[s] = g_sumy[s] / c;
    float sm = g_sumsig[s] / c;
    g_smean[s] = sm;
    g_sexp[s] = expf(10.0f * sm);
}

// ---------------- kernel: per-pixel main pass -> histogram ----------------
__global__ void k_main(const float* __restrict__ pred, const int* __restrict__ ins,
                       const int* __restrict__ lab) {
    int b = blockIdx.y;
    int p = blockIdx.x * 256 + threadIdx.x;

    __shared__ float s_cx[KK], s_cy[KK], s_sx[KK], s_sm[KK];
    __shared__ float s_var[KK], s_fg[KK];
    __shared__ float s_bg;
    if (threadIdx.x < KK) {
        int s = b * KK + threadIdx.x;
        s_cx[threadIdx.x] = g_cx[s];
        s_cy[threadIdx.x] = g_cy[s];
        s_sx[threadIdx.x] = g_sexp[s];
        s_sm[threadIdx.x] = g_smean[s];
        s_var[threadIdx.x] = 0.f;
        s_fg[threadIdx.x] = 0.f;
    }
    if (threadIdx.x == 0) s_bg = 0.f;
    __syncthreads();

    const float* pb = pred + (size_t)b * 4 * NPIX;
    float p0 = pb[p];
    float p1 = pb[NPIX + p];
    float sig = pb[2 * NPIX + p];
    float p3 = pb[3 * NPIX + p];
    int id = ins[(size_t)b * NPIX + p];
    int lb = lab[(size_t)b * NPIX + p];

    float ex = tanhf(p0) + (float)(p & (WW - 1)) * XSTEP;
    float ey = tanhf(p1) + (float)(p >> 10) * YSTEP;
    float seed = 1.0f / (1.0f + expf(-p3));

    // bg seed loss: warp reduce then one shared atomic per warp
    {
        float v = (lb == 0) ? seed * seed : 0.f;
#pragma unroll
        for (int o = 16; o > 0; o >>= 1) v += __shfl_down_sync(0xffffffffu, v, o);
        if ((threadIdx.x & 31) == 0) atomicAdd(&s_bg, v);
    }

    int myk = (id > 0 && id <= KK) ? id - 1 : -1;
    if (myk >= 0) {
        float dv = sig - s_sm[myk];
        atomicAdd(&s_var[myk], dv * dv);
    }

    unsigned long long* hb = g_hist + (size_t)(b * KK) * QBIN;
#pragma unroll
    for (int k = 0; k < KK; k++) {
        float dx = ex - s_cx[k];
        float dy = ey - s_cy[k];
        float d2 = dx * dx + dy * dy;
        float dist = __expf(-s_sx[k] * d2);
        int l = (k == myk) ? 1 : 0;
        float e = l ? (2.0f - 2.0f * dist) : (2.0f * dist);   // lovasz error, >= 0
        int bin = (int)(e * 32768.0f);
        if (bin > QBIN - 1) bin = QBIN - 1;
        int r = (QBIN - 1) - bin;                              // rank: 0 = largest error
        // rank Q-1 (e ~ 0) only influences the final jaccard value, which is
        // analytically 1 -> skip its atomic entirely (also kills the e==0 hotspot)
        if (r < QBIN - 1) {
            unsigned long long inc = 1ull | ((unsigned long long)l << 32);
            atomicAdd(hb + (size_t)k * QBIN + r, inc);
        }
        if (l) {
            float df = seed - dist;
            atomicAdd(&s_fg[myk], df * df);
        }
    }
    __syncthreads();
    if (threadIdx.x < KK) {
        int s = b * KK + threadIdx.x;
        atomicAdd(&g_var[s], (double)s_var[threadIdx.x]);
        atomicAdd(&g_fg[s], (double)s_fg[threadIdx.x]);
    }
    if (threadIdx.x == 0) atomicAdd(&g_bg[b], (double)s_bg);
}

// ---------------- reduce / scan helpers ----------------
__device__ __forceinline__ float block_reduce_f(float v, float* sh) {
    int lane = threadIdx.x & 31, wid = threadIdx.x >> 5;
#pragma unroll
    for (int o = 16; o > 0; o >>= 1) v += __shfl_down_sync(0xffffffffu, v, o);
    if (lane == 0) sh[wid] = v;
    __syncthreads();
    if (wid == 0) {
        v = (lane < (blockDim.x >> 5)) ? sh[lane] : 0.f;
#pragma unroll
        for (int o = 4; o > 0; o >>= 1) v += __shfl_down_sync(0xffffffffu, v, o);
    }
    return v;
}

// exclusive prefix across 256 threads; ws must be int[8], unique per call
__device__ __forceinline__ int block_excl_scan(int v, int* ws) {
    int lane = threadIdx.x & 31, wid = threadIdx.x >> 5;
    int x = v;
#pragma unroll
    for (int o = 1; o < 32; o <<= 1) {
        int y = __shfl_up_sync(0xffffffffu, x, o);
        if (lane >= o) x += y;
    }
    if (lane == 31) ws[wid] = x;
    __syncthreads();
    if (threadIdx.x < 8) {
        int w = ws[threadIdx.x];
#pragma unroll
        for (int o = 1; o < 8; o <<= 1) {
            int y = __shfl_up_sync(0x000000ffu, w, o);
            if ((int)threadIdx.x >= o) w += y;
        }
        ws[threadIdx.x] = w;
    }
    __syncthreads();
    return x - v + (wid > 0 ? ws[wid - 1] : 0);
}

// ---------------- kernel: per-chunk (ctot, cfg) sums ----------------
__global__ void k_bsum() {
    int chunk = blockIdx.x;
    const unsigned long long* h = g_hist + (size_t)chunk * CH + (size_t)threadIdx.x * 8;
    const ulonglong2* hp = (const ulonglong2*)h;
    unsigned int tT = 0, tF = 0;
#pragma unroll
    for (int j = 0; j < 4; j++) {
        ulonglong2 v = hp[j];
        tT += (unsigned int)v.x + (unsigned int)v.y;
        tF += (unsigned int)(v.x >> 32) + (unsigned int)(v.y >> 32);
    }
    __shared__ float sh[8];
    float rT = block_reduce_f((float)tT, sh);   // counts < 2^24, exact in fp32
    __syncthreads();
    float rF = block_reduce_f((float)tF, sh);
    if (threadIdx.x == 0) {
        g_chT[chunk] = (unsigned int)rT;
        g_chF[chunk] = (unsigned int)rF;
    }
}

// ---------------- kernel: per-segment exclusive prefix over chunks ----------------
__global__ void k_bscan() {
    int s = threadIdx.x;
    if (s >= NSEG) return;
    unsigned int oT = 0, oF = 0;
    for (int c = 0; c < CPSG; c++) {
        int i = s * CPSG + c;
        g_offT[i] = oT; g_offF[i] = oF;
        oT += g_chT[i]; oF += g_chF[i];
    }
}

// ---------------- kernel: Lovasz via jaccard prefix over bins ----------------
// loss_seg = DELTA * (Sum_r J(r)) - DELTA/2, with J(Q-1) = 1 analytic.
__global__ void k_bloss() {
    int chunk = blockIdx.x;
    int seg = chunk >> 5;                 // CPSG = 32
    unsigned int G = g_cnt[seg];
    if (G == 0) return;

    const unsigned long long* h = g_hist + (size_t)chunk * CH + (size_t)threadIdx.x * 8;
    const ulonglong2* hp = (const ulonglong2*)h;
    unsigned long long v[8];
#pragma unroll
    for (int j = 0; j < 4; j++) {
        ulonglong2 t = hp[j];
        v[2 * j] = t.x; v[2 * j + 1] = t.y;
    }
    int tT = 0, tF = 0;
#pragma unroll
    for (int j = 0; j < 8; j++) {
        tT += (int)(unsigned int)v[j];
        tF += (int)(unsigned int)(v[j] >> 32);
    }
    __shared__ int ws1[8], ws2[8];
    int eT = block_excl_scan(tT, ws1);
    __syncthreads();
    int eF = block_excl_scan(tF, ws2);

    unsigned int T = g_offT[chunk] + (unsigned int)eT;
    unsigned int F = g_offF[chunk] + (unsigned int)eF;
    float fG = (float)G;
    bool lastThread = ((chunk & 31) == 31) && (threadIdx.x == 255);

    float acc = 0.f;
#pragma unroll
    for (int j = 0; j < 8; j++) {
        T += (unsigned int)v[j];
        F += (unsigned int)(v[j] >> 32);
        float fF = (float)F, fT = (float)T;
        float J = 1.0f - __fdividef(fG - fF, fG + fT - fF);
        // global last bin (rank Q-1): counts were not histogrammed; its true
        // jaccard is analytically 1.0, added in k_final instead.
        if (!(lastThread && j == 7)) acc += J;
    }
    __shared__ float sh[8];
    float r = block_reduce_f(acc, sh);
    if (threadIdx.x == 0) atomicAdd(&g_lovS[seg], (double)r);
}

// ---------------- kernel: final combination ----------------
__global__ void k_final(float* __restrict__ out) {
    if (threadIdx.x != 0) return;
    double tot = 0.0;
    for (int b = 0; b < BB; b++) {
        int np = 0;
        double inst = 0.0, var = 0.0, fg = 0.0;
        for (int k = 0; k < KK; k++) {
            int s = b * KK + k;
            unsigned int c = g_cnt[s];
            if (c > 0) {
                np++;
                // + 1.0 = analytic J(Q-1)
                inst += (double)DELTA * (g_lovS[s] + 1.0) - 0.5 * (double)DELTA;
                var += g_var[s] / (double)c;
                fg += g_fg[s];
            }
        }
        double objf = (np > 0) ? (double)np : 1.0;
        double seed = (g_bg[b] + fg) / (double)NPIX;            // FG_W = 1
        tot += inst / objf + 10.0 * var / objf + seed;          // W_INST=1, W_VAR=10, W_SEED=1
    }
    out[0] = (float)(tot / BB);
}

// ---------------- launch ----------------
extern "C" void kernel_launch(void* const* d_in, const int* in_sizes, int n_in,
                              void* d_out, int out_size) {
    const float* pred = (const float*)d_in[0];
    const int* ins = (const int*)d_in[1];
    const int* lab = (const int*)d_in[2];
    float* out = (float*)d_out;
    cudaStream_t st = 0;

    k_zero<<<1, 64, 0, st>>>();
    k_hzero<<<(int)((size_t)NSEG * QBIN / 512), 256, 0, st>>>();
    k_stats<<<dim3(NPIX / 2048, BB), 256, 0, st>>>(pred, ins);
    k_centers<<<1, 32, 0, st>>>();
    k_main<<<dim3(NPIX / 256, BB), 256, 0, st>>>(pred, ins, lab);
    k_bsum<<<NCHB, 256, 0, st>>>();
    k_bscan<<<1, 32, 0, st>>>();
    k_bloss<<<NCHB, 256, 0, st>>>();
    k_final<<<1, 32, 0, st>>>(out);
}

// round 3
// speedup vs baseline: 6.9167x; 1.0928x over previous
#include <cuda_runtime.h>

// ---------------- problem constants ----------------
#define BB 4
#define KK 8
#define HH 512
#define WW 1024
#define NPIX (HH * WW)                 // 524288
#define NSEG (BB * KK)                 // 32
#define QBIN 4096                      // error-quantization bins
#define QSH 12
#define DELTA (2.0 / 4096.0)           // bin width over e in [0,2]

#define XSTEP (2.0f / 2047.0f)         // linspace(0,2,2048)
#define YSTEP (1.0f / 1023.0f)         // linspace(0,1,1024)

// ---------------- static device scratch ----------------
// hist[seg][r]: r = rank (0 = largest error). Packed u64: ctot lo32, cfg hi32.
__device__ unsigned long long g_hist[(size_t)NSEG * QBIN];   // 1 MB
__device__ unsigned int g_cnt[NSEG];
__device__ float g_sumx[NSEG], g_sumy[NSEG], g_sumsig[NSEG];
__device__ double g_bg[BB];
__device__ double g_var[NSEG], g_fg[NSEG], g_lovS[NSEG];

// ---------------- fast math helpers ----------------
__device__ __forceinline__ float ex2_fast(float x) {
    float r;
    asm("ex2.approx.f32 %0, %1;" : "=f"(r) : "f"(x));
    return r;
}
// tanh via exp: (e^2x - 1)/(e^2x + 1), ~1e-6 accurate
__device__ __forceinline__ float tanh_fast(float x) {
    x = fminf(fmaxf(x, -15.f), 15.f);
    float t = __expf(2.f * x);
    return __fdividef(t - 1.f, t + 1.f);
}

// ---------------- kernel: init (hist + scalars) ----------------
__global__ void k_init() {
    size_t i = ((size_t)blockIdx.x * 256 + threadIdx.x) * 2;
    ulonglong2 z; z.x = 0ull; z.y = 0ull;
    *(ulonglong2*)(g_hist + i) = z;
    if (blockIdx.x == 0) {
        int t = threadIdx.x;
        if (t < NSEG) {
            g_cnt[t] = 0u;
            g_sumx[t] = 0.f; g_sumy[t] = 0.f; g_sumsig[t] = 0.f;
            g_var[t] = 0.0; g_fg[t] = 0.0;
        }
        if (t < BB) g_bg[t] = 0.0;
    }
}

// ---------------- kernel: per-(b,k) mask statistics ----------------
__global__ void k_stats(const float* __restrict__ pred, const int* __restrict__ ins) {
    int b = blockIdx.y;
    __shared__ unsigned int s_c[8][KK];
    __shared__ float s_x[8][KK], s_y[8][KK], s_s[8][KK];
    if (threadIdx.x < 64) {
        int w = threadIdx.x >> 3, k = threadIdx.x & 7;
        s_c[w][k] = 0u; s_x[w][k] = 0.f; s_y[w][k] = 0.f; s_s[w][k] = 0.f;
    }
    __syncthreads();

    int w = threadIdx.x >> 5;
    const float* sigma = pred + ((size_t)b * 4 + 2) * NPIX;
    const int* ib = ins + (size_t)b * NPIX;
    int base = blockIdx.x * 2048;
#pragma unroll
    for (int j = 0; j < 8; j++) {
        int p = base + j * 256 + threadIdx.x;
        int id = ib[p];
        if (id > 0) {
            int k = id - 1;
            atomicAdd(&s_c[w][k], 1u);
            atomicAdd(&s_x[w][k], (float)(p & (WW - 1)) * XSTEP);
            atomicAdd(&s_y[w][k], (float)(p >> 10) * YSTEP);
            atomicAdd(&s_s[w][k], sigma[p]);
        }
    }
    __syncthreads();
    if (threadIdx.x < KK) {
        int k = threadIdx.x;
        unsigned int c = 0; float x = 0.f, y = 0.f, sg = 0.f;
#pragma unroll
        for (int ww = 0; ww < 8; ww++) {
            c += s_c[ww][k]; x += s_x[ww][k]; y += s_y[ww][k]; sg += s_s[ww][k];
        }
        int s = b * KK + k;
        atomicAdd(&g_cnt[s], c);
        atomicAdd(&g_sumx[s], x);
        atomicAdd(&g_sumy[s], y);
        atomicAdd(&g_sumsig[s], sg);
    }
}

// ---------------- kernel: per-pixel main pass -> histogram ----------------
// per k: bin4096(e) computed as ex2(A + B*ex + C*ey + D*(ex^2+ey^2)):
//   A = 12 - a*log2e*(cx^2+cy^2), B = 2a*log2e*cx, C = 2a*log2e*cy, D = -a*log2e
//   (the +12 folds the *4096 quantizer into the exponent)
__global__ void k_main(const float* __restrict__ pred, const int* __restrict__ ins,
                       const int* __restrict__ lab) {
    int b = blockIdx.y;

    __shared__ float sA[KK], sB[KK], sC[KK], sD[KK], sSM[KK];
    __shared__ float s_var[KK], s_fg[KK];
    __shared__ float s_bg;
    if (threadIdx.x < KK) {
        int s = b * KK + threadIdx.x;
        float c = fmaxf((float)g_cnt[s], 1.0f);
        float cx = g_sumx[s] / c;
        float cy = g_sumy[s] / c;
        float sm = g_sumsig[s] / c;
        float aL = expf(10.0f * sm) * 1.4426950408889634f;
        sA[threadIdx.x] = 12.0f - aL * (cx * cx + cy * cy);
        sB[threadIdx.x] = 2.0f * aL * cx;
        sC[threadIdx.x] = 2.0f * aL * cy;
        sD[threadIdx.x] = -aL;
        sSM[threadIdx.x] = sm;
        s_var[threadIdx.x] = 0.f;
        s_fg[threadIdx.x] = 0.f;
    }
    if (threadIdx.x == 0) s_bg = 0.f;
    __syncthreads();

    float A[KK], B[KK], C[KK], D[KK];
#pragma unroll
    for (int k = 0; k < KK; k++) {
        A[k] = sA[k]; B[k] = sB[k]; C[k] = sC[k]; D[k] = sD[k];
    }

    const float* pb = pred + (size_t)b * 4 * NPIX;
    const int* insb = ins + (size_t)b * NPIX;
    const int* labb = lab + (size_t)b * NPIX;
    unsigned segbase = (unsigned)(b * KK) << QSH;
    float bgacc = 0.f;

#pragma unroll
    for (int half = 0; half < 2; half++) {
        int p = blockIdx.x * 512 + half * 256 + threadIdx.x;
        float q0 = pb[p];
        float q1 = pb[NPIX + p];
        float sig = pb[2 * NPIX + p];
        float q3 = pb[3 * NPIX + p];
        int id = insb[p];
        int lb = labb[p];

        float ex = tanh_fast(q0) + (float)(p & (WW - 1)) * XSTEP;
        float ey = tanh_fast(q1) + (float)(p >> 10) * YSTEP;
        float seed = __fdividef(1.0f, 1.0f + __expf(-q3));
        if (lb == 0) bgacc += seed * seed;

        int myk = id - 1;                  // -1 if background
        float exy2 = fmaf(ex, ex, ey * ey);
        float distmy = 0.f;
#pragma unroll
        for (int k = 0; k < KK; k++) {
            float t = fmaf(D[k], exy2, fmaf(B[k], ex, fmaf(C[k], ey, A[k])));
            float d4096 = ex2_fast(t);     // dist * 4096
            bool fg = (k == myk);
            if (fg) distmy = d4096;
            float binf = fg ? (4096.0f - d4096) : d4096;
            int bin = (int)binf;
            bin = min(max(bin, 0), QBIN - 1);
            int r = (QBIN - 1) - bin;      // rank: 0 = largest error
            // rank QBIN-1 (e ~ 0): final jaccard is analytically 1 -> skip atomic
            if (r < QBIN - 1) {
                atomicAdd(&g_hist[segbase + ((unsigned)k << QSH) + (unsigned)r],
                          1ull + ((unsigned long long)fg << 32));
            }
        }
        if ((unsigned)myk < (unsigned)KK) {
            float dv = sig - sSM[myk];
            atomicAdd(&s_var[myk], dv * dv);
            float df = fmaf(distmy, -(1.0f / 4096.0f), seed);
            atomicAdd(&s_fg[myk], df * df);
        }
    }

    // warp-reduce bg then one shared atomic per warp
#pragma unroll
    for (int o = 16; o > 0; o >>= 1) bgacc += __shfl_down_sync(0xffffffffu, bgacc, o);
    if ((threadIdx.x & 31) == 0) atomicAdd(&s_bg, bgacc);

    __syncthreads();
    if (threadIdx.x < KK) {
        int s = b * KK + threadIdx.x;
        atomicAdd(&g_var[s], (double)s_var[threadIdx.x]);
        atomicAdd(&g_fg[s], (double)s_fg[threadIdx.x]);
    }
    if (threadIdx.x == 0) atomicAdd(&g_bg[b], (double)s_bg);
}

// ---------------- kernel: per-segment Lovasz via jaccard prefix ----------------
// one block (512 threads x 8 bins) per segment; no atomics, single pass
__device__ __forceinline__ int bscan_excl512(int v, int* ws) {
    int lane = threadIdx.x & 31, wid = threadIdx.x >> 5;
    int x = v;
#pragma unroll
    for (int o = 1; o < 32; o <<= 1) {
        int y = __shfl_up_sync(0xffffffffu, x, o);
        if (lane >= o) x += y;
    }
    if (lane == 31) ws[wid] = x;
    __syncthreads();
    if (threadIdx.x < 32) {
        int w = (threadIdx.x < 16) ? ws[threadIdx.x] : 0;
#pragma unroll
        for (int o = 1; o < 16; o <<= 1) {
            int y = __shfl_up_sync(0xffffffffu, w, o);
            if ((int)threadIdx.x >= o) w += y;
        }
        if (threadIdx.x < 16) ws[threadIdx.x] = w;
    }
    __syncthreads();
    return x - v + (wid > 0 ? ws[wid - 1] : 0);
}

__global__ void k_tail() {
    int seg = blockIdx.x;
    unsigned int G = g_cnt[seg];
    if (G == 0) return;                        // absent instance

    const ulonglong2* hp =
        (const ulonglong2*)(g_hist + ((size_t)seg << QSH) + (size_t)threadIdx.x * 8);
    unsigned long long v[8];
#pragma unroll
    for (int j = 0; j < 4; j++) {
        ulonglong2 t = hp[j];
        v[2 * j] = t.x; v[2 * j + 1] = t.y;
    }
    int tT = 0, tF = 0;
#pragma unroll
    for (int j = 0; j < 8; j++) {
        tT += (int)(unsigned int)v[j];
        tF += (int)(unsigned int)(v[j] >> 32);
    }
    __shared__ int ws[32];
    int eT = bscan_excl512(tT, ws);
    __syncthreads();
    int eF = bscan_excl512(tF, ws);

    float fG = (float)G;
    unsigned int T = (unsigned int)eT, F = (unsigned int)eF;
    bool lastT = (threadIdx.x == 511);
    float acc = 0.f;
#pragma unroll
    for (int j = 0; j < 8; j++) {
        T += (unsigned int)v[j];
        F += (unsigned int)(v[j] >> 32);
        float J = 1.0f - __fdividef(fG - (float)F, fG + (float)T - (float)F);
        // global last bin: counts not histogrammed; true J = 1, added in k_final
        if (!(lastT && j == 7)) acc += J;
    }
    // block reduce 512
    int lane = threadIdx.x & 31, wid = threadIdx.x >> 5;
#pragma unroll
    for (int o = 16; o > 0; o >>= 1) acc += __shfl_down_sync(0xffffffffu, acc, o);
    __shared__ float sh[16];
    if (lane == 0) sh[wid] = acc;
    __syncthreads();
    if (threadIdx.x < 32) {
        float r = (threadIdx.x < 16) ? sh[threadIdx.x] : 0.f;
#pragma unroll
        for (int o = 8; o > 0; o >>= 1) r += __shfl_down_sync(0xffffffffu, r, o);
        if (threadIdx.x == 0) g_lovS[seg] = (double)r;
    }
}

// ---------------- kernel: final combination ----------------
__global__ void k_final(float* __restrict__ out) {
    if (threadIdx.x != 0) return;
    double tot = 0.0;
    for (int b = 0; b < BB; b++) {
        int np = 0;
        double inst = 0.0, var = 0.0, fg = 0.0;
        for (int k = 0; k < KK; k++) {
            int s = b * KK + k;
            unsigned int c = g_cnt[s];
            if (c > 0) {
                np++;
                inst += DELTA * (g_lovS[s] + 1.0) - 0.5 * DELTA;  // +1 = analytic J(Q-1)
                var += g_var[s] / (double)c;
                fg += g_fg[s];
            }
        }
        double objf = (np > 0) ? (double)np : 1.0;
        double seed = (g_bg[b] + fg) / (double)NPIX;             // FG_W = 1
        tot += inst / objf + 10.0 * var / objf + seed;           // W_INST=1, W_VAR=10, W_SEED=1
    }
    out[0] = (float)(tot / BB);
}

// ---------------- launch ----------------
extern "C" void kernel_launch(void* const* d_in, const int* in_sizes, int n_in,
                              void* d_out, int out_size) {
    const float* pred = (const float*)d_in[0];
    const int* ins = (const int*)d_in[1];
    const int* lab = (const int*)d_in[2];
    float* out = (float*)d_out;
    cudaStream_t st = 0;

    k_init<<<(int)((size_t)NSEG * QBIN / 512), 256, 0, st>>>();
    k_stats<<<dim3(NPIX / 2048, BB), 256, 0, st>>>(pred, ins);
    k_main<<<dim3(NPIX / 512, BB), 256, 0, st>>>(pred, ins, lab);
    k_tail<<<NSEG, 512, 0, st>>>();
    k_final<<<1, 32, 0, st>>>(out);
}

// round 4
// speedup vs baseline: 7.0730x; 1.0226x over previous
#include <cuda_runtime.h>

// ---------------- problem constants ----------------
#define BB 4
#define KK 8
#define HH 512
#define WW 1024
#define NPIX (HH * WW)                 // 524288
#define NSEG (BB * KK)                 // 32
#define QBIN 4096                      // error-quantization bins
#define QSH 12
#define DELTA (2.0 / 4096.0)           // bin width over e in [0,2]

#define XSTEP (2.0f / 2047.0f)         // linspace(0,2,2048)
#define YSTEP (1.0f / 1023.0f)         // linspace(0,1,1024)

// ---------------- static device scratch ----------------
// hist[seg][r]: r = rank (0 = largest error). Packed u64: ctot lo32, cfg hi32.
__device__ unsigned long long g_hist[(size_t)NSEG * QBIN];   // 1 MB
__device__ unsigned int g_cnt[NSEG];
__device__ float g_sumx[NSEG], g_sumy[NSEG], g_sumsig[NSEG];
__device__ double g_bg[BB];
__device__ double g_var[NSEG], g_fg[NSEG], g_lovS[NSEG];
__device__ unsigned int g_done;        // completion ticket (zero-init, self-resetting)

// ---------------- fast math helpers ----------------
__device__ __forceinline__ float ex2_fast(float x) {
    float r;
    asm("ex2.approx.f32 %0, %1;" : "=f"(r) : "f"(x));
    return r;
}
// tanh via exp: (e^2x - 1)/(e^2x + 1), ~1e-6 accurate
__device__ __forceinline__ float tanh_fast(float x) {
    x = fminf(fmaxf(x, -15.f), 15.f);
    float t = __expf(2.f * x);
    return __fdividef(t - 1.f, t + 1.f);
}

// ---------------- kernel 1: hist zero + per-(b,k) mask statistics ----------------
// grid (256, BB) x 256 thr; each of the 1024 blocks also zeroes 128 u64 of g_hist
__global__ void __launch_bounds__(256) k_stats(const float* __restrict__ pred,
                                               const int* __restrict__ ins) {
    int b = blockIdx.y;
    int fb = b * gridDim.x + blockIdx.x;          // 0..1023

    // zero my 128-u64 slice of the histogram (64 threads x ulonglong2)
    if (threadIdx.x < 64) {
        ulonglong2 z; z.x = 0ull; z.y = 0ull;
        *(ulonglong2*)(g_hist + (size_t)fb * 128 + (size_t)threadIdx.x * 2) = z;
    }
    if (fb == 0) {
        int t = threadIdx.x;
        if (t < NSEG) {
            g_cnt[t] = 0u;
            g_sumx[t] = 0.f; g_sumy[t] = 0.f; g_sumsig[t] = 0.f;
            g_var[t] = 0.0; g_fg[t] = 0.0;
        }
        if (t < BB) g_bg[t] = 0.0;
        if (t == 0) g_done = 0u;
    }

    __shared__ unsigned int s_c[8][KK];
    __shared__ float s_x[8][KK], s_y[8][KK], s_s[8][KK];
    if (threadIdx.x < 64) {
        int w = threadIdx.x >> 3, k = threadIdx.x & 7;
        s_c[w][k] = 0u; s_x[w][k] = 0.f; s_y[w][k] = 0.f; s_s[w][k] = 0.f;
    }
    __syncthreads();

    int w = threadIdx.x >> 5;
    const float* sigma = pred + ((size_t)b * 4 + 2) * NPIX;
    const int* ib = ins + (size_t)b * NPIX;
    int p0 = blockIdx.x * 2048 + threadIdx.x * 8;   // 8 px per thread
    const int4* ip = (const int4*)(ib + p0);
    const float4* sp = (const float4*)(sigma + p0);
#pragma unroll
    for (int v = 0; v < 2; v++) {
        int4 id4 = ip[v];
        float4 s4 = sp[v];
        int ids[4] = {id4.x, id4.y, id4.z, id4.w};
        float sg[4] = {s4.x, s4.y, s4.z, s4.w};
#pragma unroll
        for (int j = 0; j < 4; j++) {
            int p = p0 + v * 4 + j;
            int id = ids[j];
            if (id > 0) {
                int k = id - 1;
                atomicAdd(&s_c[w][k], 1u);
                atomicAdd(&s_x[w][k], (float)(p & (WW - 1)) * XSTEP);
                atomicAdd(&s_y[w][k], (float)(p >> 10) * YSTEP);
                atomicAdd(&s_s[w][k], sg[j]);
            }
        }
    }
    __syncthreads();
    if (threadIdx.x < KK) {
        int k = threadIdx.x;
        unsigned int c = 0; float x = 0.f, y = 0.f, sg = 0.f;
#pragma unroll
        for (int ww = 0; ww < 8; ww++) {
            c += s_c[ww][k]; x += s_x[ww][k]; y += s_y[ww][k]; sg += s_s[ww][k];
        }
        int s = b * KK + k;
        atomicAdd(&g_cnt[s], c);
        atomicAdd(&g_sumx[s], x);
        atomicAdd(&g_sumy[s], y);
        atomicAdd(&g_sumsig[s], sg);
    }
}

// ---------------- kernel 2: per-pixel main pass -> histogram ----------------
// per k: bin4096(e) = ex2(A + B*ex + C*ey + D*(ex^2+ey^2)), quantizer folded in exponent
__global__ void __launch_bounds__(256) k_main(const float* __restrict__ pred,
                                              const int* __restrict__ ins,
                                              const int* __restrict__ lab) {
    int b = blockIdx.y;

    __shared__ float sA[KK], sB[KK], sC[KK], sD[KK], sSM[KK];
    __shared__ float s_var[KK], s_fg[KK];
    __shared__ float s_bg;
    if (threadIdx.x < KK) {
        int s = b * KK + threadIdx.x;
        float c = fmaxf((float)g_cnt[s], 1.0f);
        float cx = g_sumx[s] / c;
        float cy = g_sumy[s] / c;
        float sm = g_sumsig[s] / c;
        float aL = expf(10.0f * sm) * 1.4426950408889634f;
        sA[threadIdx.x] = 12.0f - aL * (cx * cx + cy * cy);
        sB[threadIdx.x] = 2.0f * aL * cx;
        sC[threadIdx.x] = 2.0f * aL * cy;
        sD[threadIdx.x] = -aL;
        sSM[threadIdx.x] = sm;
        s_var[threadIdx.x] = 0.f;
        s_fg[threadIdx.x] = 0.f;
    }
    if (threadIdx.x == 0) s_bg = 0.f;
    __syncthreads();

    float A[KK], B[KK], C[KK], D[KK];
#pragma unroll
    for (int k = 0; k < KK; k++) {
        A[k] = sA[k]; B[k] = sB[k]; C[k] = sC[k]; D[k] = sD[k];
    }

    const float* pb = pred + (size_t)b * 4 * NPIX;
    unsigned segbase = (unsigned)(b * KK) << QSH;

    int p0 = (blockIdx.x * 256 + threadIdx.x) * 4;   // 4 px per thread
    float4 q0 = *(const float4*)(pb + p0);
    float4 q1 = *(const float4*)(pb + NPIX + p0);
    float4 qs = *(const float4*)(pb + 2 * NPIX + p0);
    float4 q3 = *(const float4*)(pb + 3 * NPIX + p0);
    int4 id4 = *(const int4*)(ins + (size_t)b * NPIX + p0);
    int4 lb4 = *(const int4*)(lab + (size_t)b * NPIX + p0);

    float q0a[4] = {q0.x, q0.y, q0.z, q0.w};
    float q1a[4] = {q1.x, q1.y, q1.z, q1.w};
    float qsa[4] = {qs.x, qs.y, qs.z, qs.w};
    float q3a[4] = {q3.x, q3.y, q3.z, q3.w};
    int ida[4] = {id4.x, id4.y, id4.z, id4.w};
    int lba[4] = {lb4.x, lb4.y, lb4.z, lb4.w};

    float bgacc = 0.f;
    float fx = (float)(p0 & (WW - 1)) * XSTEP;       // 4 px never cross a row (W mult of 4)
    float fy = (float)(p0 >> 10) * YSTEP;

#pragma unroll
    for (int j = 0; j < 4; j++) {
        float ex = tanh_fast(q0a[j]) + fx + (float)j * XSTEP;
        float ey = tanh_fast(q1a[j]) + fy;
        float seed = __fdividef(1.0f, 1.0f + __expf(-q3a[j]));
        if (lba[j] == 0) bgacc += seed * seed;

        int myk = ida[j] - 1;                        // -1 if background
        float exy2 = fmaf(ex, ex, ey * ey);
        float distmy = 0.f;
#pragma unroll
        for (int k = 0; k < KK; k++) {
            float t = fmaf(D[k], exy2, fmaf(B[k], ex, fmaf(C[k], ey, A[k])));
            float d4096 = ex2_fast(t);               // dist * 4096
            bool fg = (k == myk);
            if (fg) distmy = d4096;
            float binf = fg ? (4096.0f - d4096) : d4096;
            int bin = min(max((int)binf, 0), QBIN - 1);
            int r = (QBIN - 1) - bin;                // rank: 0 = largest error
            // rank QBIN-1 (e ~ 0): final jaccard analytically 1 -> skip atomic
            if (r < QBIN - 1) {
                atomicAdd(&g_hist[segbase + ((unsigned)k << QSH) + (unsigned)r],
                          1ull + ((unsigned long long)fg << 32));
            }
        }
        if ((unsigned)myk < (unsigned)KK) {
            float dv = qsa[j] - sSM[myk];
            atomicAdd(&s_var[myk], dv * dv);
            float df = fmaf(distmy, -(1.0f / 4096.0f), seed);
            atomicAdd(&s_fg[myk], df * df);
        }
    }

#pragma unroll
    for (int o = 16; o > 0; o >>= 1) bgacc += __shfl_down_sync(0xffffffffu, bgacc, o);
    if ((threadIdx.x & 31) == 0) atomicAdd(&s_bg, bgacc);

    __syncthreads();
    if (threadIdx.x < KK) {
        int s = b * KK + threadIdx.x;
        atomicAdd(&g_var[s], (double)s_var[threadIdx.x]);
        atomicAdd(&g_fg[s], (double)s_fg[threadIdx.x]);
    }
    if (threadIdx.x == 0) atomicAdd(&g_bg[b], (double)s_bg);
}

// ---------------- kernel 3: Lovasz prefix + final combine (ticketed) ----------------
__device__ __forceinline__ int bscan_excl512(int v, int* ws) {
    int lane = threadIdx.x & 31, wid = threadIdx.x >> 5;
    int x = v;
#pragma unroll
    for (int o = 1; o < 32; o <<= 1) {
        int y = __shfl_up_sync(0xffffffffu, x, o);
        if (lane >= o) x += y;
    }
    if (lane == 31) ws[wid] = x;
    __syncthreads();
    if (threadIdx.x < 32) {
        int w = (threadIdx.x < 16) ? ws[threadIdx.x] : 0;
#pragma unroll
        for (int o = 1; o < 16; o <<= 1) {
            int y = __shfl_up_sync(0xffffffffu, w, o);
            if ((int)threadIdx.x >= o) w += y;
        }
        if (threadIdx.x < 16) ws[threadIdx.x] = w;
    }
    __syncthreads();
    return x - v + (wid > 0 ? ws[wid - 1] : 0);
}

__global__ void __launch_bounds__(512) k_tail(float* __restrict__ out) {
    int seg = blockIdx.x;
    unsigned int G = g_cnt[seg];

    if (G > 0) {
        const ulonglong2* hp =
            (const ulonglong2*)(g_hist + ((size_t)seg << QSH) + (size_t)threadIdx.x * 8);
        unsigned long long v[8];
#pragma unroll
        for (int j = 0; j < 4; j++) {
            ulonglong2 t = hp[j];
            v[2 * j] = t.x; v[2 * j + 1] = t.y;
        }
        int tT = 0, tF = 0;
#pragma unroll
        for (int j = 0; j < 8; j++) {
            tT += (int)(unsigned int)v[j];
            tF += (int)(unsigned int)(v[j] >> 32);
        }
        __shared__ int ws[32];
        int eT = bscan_excl512(tT, ws);
        __syncthreads();
        int eF = bscan_excl512(tF, ws);

        float fG = (float)G;
        unsigned int T = (unsigned int)eT, F = (unsigned int)eF;
        bool lastT = (threadIdx.x == 511);
        float acc = 0.f;
#pragma unroll
        for (int j = 0; j < 8; j++) {
            T += (unsigned int)v[j];
            F += (unsigned int)(v[j] >> 32);
            float J = 1.0f - __fdividef(fG - (float)F, fG + (float)T - (float)F);
            // global last bin: counts not histogrammed; true J = 1, added below
            if (!(lastT && j == 7)) acc += J;
        }
        int lane = threadIdx.x & 31, wid = threadIdx.x >> 5;
#pragma unroll
        for (int o = 16; o > 0; o >>= 1) acc += __shfl_down_sync(0xffffffffu, acc, o);
        __shared__ float sh[16];
        if (lane == 0) sh[wid] = acc;
        __syncthreads();
        if (threadIdx.x < 32) {
            float r = (threadIdx.x < 16) ? sh[threadIdx.x] : 0.f;
#pragma unroll
            for (int o = 8; o > 0; o >>= 1) r += __shfl_down_sync(0xffffffffu, r, o);
            if (threadIdx.x == 0) g_lovS[seg] = (double)r;
        }
    }

    // completion ticket: last block does the final combine
    __shared__ bool s_last;
    if (threadIdx.x == 0) {
        __threadfence();
        unsigned int t = atomicAdd(&g_done, 1u);
        s_last = (t == NSEG - 1);
    }
    __syncthreads();
    if (s_last && threadIdx.x == 0) {
        __threadfence();
        double tot = 0.0;
        for (int b = 0; b < BB; b++) {
            int np = 0;
            double inst = 0.0, var = 0.0, fg = 0.0;
            for (int k = 0; k < KK; k++) {
                int s = b * KK + k;
                unsigned int c = g_cnt[s];
                if (c > 0) {
                    np++;
                    inst += DELTA * (g_lovS[s] + 1.0) - 0.5 * DELTA;  // +1 = analytic J(Q-1)
                    var += g_var[s] / (double)c;
                    fg += g_fg[s];
                }
            }
            double objf = (np > 0) ? (double)np : 1.0;
            double seedl = (g_bg[b] + fg) / (double)NPIX;            // FG_W = 1
            tot += inst / objf + 10.0 * var / objf + seedl;          // 1,10,1 weights
        }
        out[0] = (float)(tot / BB);
        g_done = 0u;   // reset for next replay
    }
}

// ---------------- launch ----------------
extern "C" void kernel_launch(void* const* d_in, const int* in_sizes, int n_in,
                              void* d_out, int out_size) {
    const float* pred = (const float*)d_in[0];
    const int* ins = (const int*)d_in[1];
    const int* lab = (const int*)d_in[2];
    float* out = (float*)d_out;
    cudaStream_t st = 0;

    k_stats<<<dim3(NPIX / 2048, BB), 256, 0, st>>>(pred, ins);
    k_main<<<dim3(NPIX / 1024, BB), 256, 0, st>>>(pred, ins, lab);
    k_tail<<<NSEG, 512, 0, st>>>(out);
}